// round 16
// baseline (speedup 1.0000x reference)
#include <cuda_runtime.h>
#include <cstdint>

// DispCorr via mma.sync tf32 m16n8k8 (base sm_103), round 16:
// m32 register blocking — each warp computes a 32(m) x 96(jl) band so one
// B fragment band serves two m16 halves: fragment LDS bytes -33% per output.
// CTA = 128 threads / 4 warps, quarter-W; __launch_bounds__(128,4) -> 4 CTAs/SM.
//
// CTA = (b, h, quarter q): w in [w0, w0+128), all d in [0,64).
//   A[m][k] = tf32(L[k][w0+m])     m in [0,128) -> smem [128][36]
//   B[n][k] = tf32(R[k][w0-64+n])  n in [0,192) -> smem [192][36] (s<0 rows zero)
// P[m,n] = sum_k A B ; out[d, w0+m] = P[m, m+64-d].
// Warp w: m0 = 32w, band jl in [0,96): 12 n-tiles x 4 k-steps x 2 halves = 96 HMMA.
// Epilogue: scatter -> ob[64][132] (aliases A/R after sync; conflict-free) -> float4 STG.

#define A_OFF   0
#define R_OFF   (128 * 36)                    // 4608 floats
#define STAGE_FLOATS (R_OFF + 192 * 36)       // 11520 floats = 46080 B
#define OB_STRIDE 132                         // ob[64][132] aliased at offset 0
#define SMEM_BYTES (STAGE_FLOATS * 4)         // 46080

#define CSTR ((size_t)131072)                 // 256*512 (channel stride)

static __device__ __forceinline__ unsigned f2tf32(float f) {
    unsigned u;
    asm("cvt.rna.tf32.f32 %0, %1;" : "=r"(u) : "f"(f));
    return u;
}

static __device__ __forceinline__ void mma16n8k8(float* c, const unsigned* a,
                                                 const unsigned* b) {
    asm volatile(
        "mma.sync.aligned.m16n8k8.row.col.f32.tf32.tf32.f32 "
        "{%0,%1,%2,%3}, {%4,%5,%6,%7}, {%8,%9}, {%0,%1,%2,%3};"
        : "+f"(c[0]), "+f"(c[1]), "+f"(c[2]), "+f"(c[3])
        : "r"(a[0]), "r"(a[1]), "r"(a[2]), "r"(a[3]), "r"(b[0]), "r"(b[1]));
}

__global__ __launch_bounds__(128, 4)
void disp_corr_mma(const float* __restrict__ x, float* __restrict__ out) {
    extern __shared__ unsigned smem_u[];
    float* smem_f = (float*)smem_u;

    const int tid  = threadIdx.x;
    const int warp = tid >> 5;       // 0..3
    const int lane = tid & 31;
    const int gid  = lane >> 2;      // fragment row group
    const int t    = lane & 3;       // fragment col group
    const int bx   = blockIdx.x;
    const int q    = bx & 3;
    const int bh   = bx >> 2;
    const int b    = bh >> 8;
    const int h    = bh & 255;
    const int w0   = q << 7;         // 0,128,256,384

    const float* xL = x + (((size_t)b * 64) * 256 + h) * 512;
    const float* xR = xL + 32 * CSTR;

    // ---- Stage 320 K-major rows: A m=0..127 (w0+m), R n=0..191 (s=w0-64+n) ----
    for (int it = tid; it < 320; it += 128) {
        unsigned a[32];
        unsigned* row;
        if (it < 128) {
            const float* g = xL + w0 + it;
#pragma unroll
            for (int c = 0; c < 32; ++c) a[c] = f2tf32(g[c * CSTR]);
            row = smem_u + A_OFF + it * 36;
        } else {
            const int n = it - 128;
            const int s = w0 - 64 + n;
            if (s < 0) {
#pragma unroll
                for (int c = 0; c < 32; ++c) a[c] = 0u;
            } else {
                const float* g = xR + s;
#pragma unroll
                for (int c = 0; c < 32; ++c) a[c] = f2tf32(g[c * CSTR]);
            }
            row = smem_u + R_OFF + n * 36;
        }
#pragma unroll
        for (int qq = 0; qq < 8; ++qq)
            *(uint4*)(row + 4 * qq) = make_uint4(a[4*qq], a[4*qq+1], a[4*qq+2], a[4*qq+3]);
    }
    __syncthreads();

    // ---- Compute: warp's m32 block m0 = 32*warp; band jl in [0,96) ----
    const int m0 = 32 * warp;
    const int abase = A_OFF + (m0 + gid) * 36 + t;
    const int bbase = R_OFF + (m0 + gid) * 36 + t;   // n = m0 + 8*nt + gid via +288*nt

    float acc[2][12][4];
#pragma unroll
    for (int hf = 0; hf < 2; ++hf)
#pragma unroll
        for (int nt = 0; nt < 12; ++nt)
#pragma unroll
            for (int e = 0; e < 4; ++e) acc[hf][nt][e] = 0.f;

#pragma unroll
    for (int ks = 0; ks < 4; ++ks) {
        // A fragments for rows gid, gid+8 (half 0) and gid+16, gid+24 (half 1)
        unsigned a0[4], a1[4];
        a0[0] = smem_u[abase + 8 * ks];
        a0[1] = smem_u[abase + 288 + 8 * ks];
        a0[2] = smem_u[abase + 8 * ks + 4];
        a0[3] = smem_u[abase + 288 + 8 * ks + 4];
        a1[0] = smem_u[abase + 576 + 8 * ks];
        a1[1] = smem_u[abase + 864 + 8 * ks];
        a1[2] = smem_u[abase + 576 + 8 * ks + 4];
        a1[3] = smem_u[abase + 864 + 8 * ks + 4];
#pragma unroll
        for (int nt = 0; nt < 12; ++nt) {
            unsigned bb[2];
            bb[0] = smem_u[bbase + nt * 288 + 8 * ks];
            bb[1] = smem_u[bbase + nt * 288 + 8 * ks + 4];
            mma16n8k8(acc[0][nt], a0, bb);
            mma16n8k8(acc[1][nt], a1, bb);
        }
    }
    __syncthreads();   // operand tiles dead; ob aliases them

    // ---- Scatter fragments to ob[d][w_loc], d = i - jl + 64 ----
    // i = 16*hf + gid + 8*(reg>>1); jl = 8*nt + 2*t + (reg&1); w_loc = m0 + i
    float* ob = smem_f;
#pragma unroll
    for (int hf = 0; hf < 2; ++hf) {
#pragma unroll
        for (int nt = 0; nt < 12; ++nt) {
#pragma unroll
            for (int reg = 0; reg < 4; ++reg) {
                const int i  = 16 * hf + gid + 8 * (reg >> 1);
                const int jl = 8 * nt + 2 * t + (reg & 1);
                const int d  = i - jl + 64;
                if ((unsigned)d < 64u)
                    ob[d * OB_STRIDE + m0 + i] = acc[hf][nt][reg];
            }
        }
    }
    __syncthreads();

    // ---- Coalesced store: 64 d-rows x 128 w (float4) ----
    const float inv_c = 1.0f / 32.0f;
    for (int it = tid; it < 2048; it += 128) {
        const int d = it >> 5, f4 = it & 31;
        float4 v = *(float4*)(ob + d * OB_STRIDE + 4 * f4);
        v.x *= inv_c; v.y *= inv_c; v.z *= inv_c; v.w *= inv_c;
        *(float4*)(out + (((size_t)b * 64 + d) * 256 + h) * 512 + w0 + 4 * f4) = v;
    }
}

extern "C" void kernel_launch(void* const* d_in, const int* in_sizes, int n_in,
                              void* d_out, int out_size) {
    const float* x = (const float*)d_in[0];
    float* out = (float*)d_out;
    (void)in_sizes; (void)n_in; (void)out_size;

    cudaFuncSetAttribute(disp_corr_mma,
                         cudaFuncAttributeMaxDynamicSharedMemorySize, SMEM_BYTES);
    disp_corr_mma<<<4096, 128, SMEM_BYTES>>>(x, out);
}